// round 9
// baseline (speedup 1.0000x reference)
#include <cuda_runtime.h>
#include <cuda_fp16.h>

#define DF   64
#define NN   100000
#define EE   1600000
#define EEP  (EE + 8 * NN)           // padded CSR capacity (rows padded to 8)
#define EPSV 1e-5f
#define WSCALE 268435456.0f          // 2^28 fixed-point weight scale
#define WINV   (1.0f / 268435456.0f)
#define QUOTA 4096                   // staged edges per agg block (32 KB smem)

// ---------------- scratch (device globals; zero-initialized at load) -------
// Invariant: every call leaves g_degcnt/g_bnsum/g_bnsq/g_scan_ctr all-zero
// (CLEAN tail in the final kernel), matching first-call zero-init. Everything
// else is fully rewritten every call (incl. g_edge pad slots, written by scan).
__device__ unsigned long long g_degcnt[NN]; // (cnt<<48) | fx28 weighted degree
__device__ float g_dinv[NN];
__device__ int   g_fill[NN];                // scan seeds with prefix; fill bumps
__device__ int   g_rowptr[NN + 1];          // padded exclusive prefix
__device__ unsigned long long g_edge[EEP];  // packed: (w_bits<<32) | src
__device__ __half g_h1[(size_t)NN * DF];    // dinv-scaled layer-1 features (fp16)
__device__ float  g_ha[(size_t)NN * DF];    // aggregated layer-1 output (fp32)
__device__ __half g_h2[(size_t)NN * DF];    // dinv-scaled layer-2 features (fp16)
__device__ float g_bnsum[DF];
__device__ float g_bnsq[DF];
__device__ int   g_part[128];
__device__ int   g_scan_ctr;

__device__ __forceinline__ unsigned long long pack_dc(float w) {
    return (1ULL << 48) | (unsigned long long)(fmaf(w, WSCALE, 0.5f));
}

// ---------------- edge pass 1: single packed atomic per edge ---------------
__global__ void k_edge_deg(const int* __restrict__ ei,
                           const float* __restrict__ w, int E) {
    int e4 = (blockIdx.x * blockDim.x + threadIdx.x) * 4;
    if (e4 + 3 < E) {
        int4   d4 = *(const int4*)&ei[E + e4];
        float4 w4 = *(const float4*)&w[e4];
        atomicAdd(&g_degcnt[d4.x], pack_dc(w4.x));
        atomicAdd(&g_degcnt[d4.y], pack_dc(w4.y));
        atomicAdd(&g_degcnt[d4.z], pack_dc(w4.z));
        atomicAdd(&g_degcnt[d4.w], pack_dc(w4.w));
    } else {
        for (int e = e4; e < E; e++)
            atomicAdd(&g_degcnt[ei[E + e]], pack_dc(w[e]));
    }
}
__global__ void k_edge_deg_s(const int* __restrict__ ei,
                             const float* __restrict__ w, int E) {
    int e = blockIdx.x * blockDim.x + threadIdx.x;
    if (e < E) atomicAdd(&g_degcnt[ei[E + e]], pack_dc(w[e]));
}

// ---------------- fused scan: dinv + padded prefix + pad-slot zeroing ------
__global__ void k_scan(int n, int nb) {
    __shared__ int s[1024];
    __shared__ int sp[128];
    int t = threadIdx.x;
    int i = blockIdx.x * 1024 + t;

    int cnt = 0, v = 0;
    if (i < n) {
        unsigned long long p = g_degcnt[i];
        cnt = (int)(p >> 48);
        float deg = (float)(long long)(p & 0xFFFFFFFFFFFFULL) * WINV;
        g_dinv[i] = rsqrtf(deg + 1.0f);        // +1 = self loop
        v = (cnt + 7) & ~7;                    // pad row to multiple of 8
    }

    // block reduce of padded counts -> publish partial
    s[t] = v;
    __syncthreads();
    for (int off = 512; off > 0; off >>= 1) {
        if (t < off) s[t] += s[t + off];
        __syncthreads();
    }
    if (t == 0) {
        g_part[blockIdx.x] = s[0];
        __threadfence();
        atomicAdd(&g_scan_ctr, 1);
    }
    __syncthreads();

    // local inclusive scan (Hillis-Steele)
    s[t] = v;
    __syncthreads();
    for (int off = 1; off < 1024; off <<= 1) {
        int a = (t >= off) ? s[t - off] : 0;
        __syncthreads();
        s[t] += a;
        __syncthreads();
    }

    // wait for all blocks' partials (single wave: nb <= 148 SMs)
    if (t == 0) {
        while (atomicAdd(&g_scan_ctr, 0) < nb) { }
    }
    __syncthreads();

    // inline prefix over partials
    if (t < 128) sp[t] = (t < nb) ? g_part[t] : 0;
    __syncthreads();
    #pragma unroll
    for (int off = 1; off < 128; off <<= 1) {
        int a = (t < 128 && t >= off) ? sp[t - off] : 0;
        __syncthreads();
        if (t < 128) sp[t] += a;
        __syncthreads();
    }

    int bp = (blockIdx.x > 0) ? sp[blockIdx.x - 1] : 0;
    if (i < n) {
        int p = bp + s[t] - v;                 // padded exclusive prefix
        g_rowptr[i] = p;
        g_fill[i]   = p;                       // seed fill cursor
        for (int k = p + cnt; k < p + v; k++)  // zero-weight pad slots
            g_edge[k] = 0ULL;
    }
    if (i == n - 1) g_rowptr[n] = bp + s[t];
}

// ---------------- edge pass 2: fill CSR (raw weight; no gathers) -----------
__device__ __forceinline__ unsigned long long pack_edge(float w, int s) {
    return ((unsigned long long)__float_as_uint(w) << 32) |
           (unsigned long long)(unsigned)s;
}
__global__ void k_fill(const int* __restrict__ ei,
                       const float* __restrict__ w, int E) {
    int e2 = (blockIdx.x * blockDim.x + threadIdx.x) * 2;
    if (e2 + 1 < E) {
        int2   sv = *(const int2*)&ei[e2];
        int2   dv = *(const int2*)&ei[E + e2];
        float2 wv = *(const float2*)&w[e2];
        int slot0 = atomicAdd(&g_fill[dv.x], 1);
        int slot1 = atomicAdd(&g_fill[dv.y], 1);
        g_edge[slot0] = pack_edge(wv.x, sv.x);
        g_edge[slot1] = pack_edge(wv.y, sv.y);
    } else if (e2 < E) {
        int slot = atomicAdd(&g_fill[ei[E + e2]], 1);
        g_edge[slot] = pack_edge(w[e2], ei[e2]);
    }
}
__global__ void k_fill_s(const int* __restrict__ ei,
                         const float* __restrict__ w, int E) {
    int e = blockIdx.x * blockDim.x + threadIdx.x;
    if (e < E) {
        int slot = atomicAdd(&g_fill[ei[E + e]], 1);
        g_edge[slot] = pack_edge(w[e], ei[e]);
    }
}

// ---------------- GEMM: Yh[N,64] = dinv .* (f(X)[N,64] @ W[64,64]) (fp16) ---
template <bool BN>
__global__ void __launch_bounds__(256) k_gemm(const float* __restrict__ X,
                                              const float* __restrict__ W,
                                              __half* __restrict__ Yh, int n,
                                              const float* __restrict__ gamma,
                                              const float* __restrict__ beta,
                                              float invn) {
    __shared__ __align__(16) float sW[64][64];
    __shared__ __align__(16) float sA[64];
    __shared__ __align__(16) float sC[64];
    int tid = threadIdx.x;

    {   // load W (4096 floats) cooperatively
        const float4* W4 = (const float4*)W;
        float4* sW4 = (float4*)&sW[0][0];
        #pragma unroll
        for (int i = 0; i < 4; i++) sW4[tid + 256 * i] = W4[tid + 256 * i];
    }
    if (BN && tid < 64) {
        float mu   = g_bnsum[tid] * invn;
        float var  = g_bnsq[tid] * invn - mu * mu;
        float a    = gamma[tid] * rsqrtf(var + EPSV);
        sA[tid] = a;
        sC[tid] = beta[tid] - mu * a;
    }
    __syncthreads();

    int rg = tid >> 3;                   // 0..31
    int cg = tid & 7;                    // 0..7
    int rbase = blockIdx.x * 128 + rg;   // rows rbase + 32*rr

    float acc[8][8];
    #pragma unroll
    for (int a = 0; a < 8; a++)
        #pragma unroll
        for (int b = 0; b < 8; b++) acc[a][b] = 0.0f;

    const float4* X4 = (const float4*)X;

    #pragma unroll
    for (int k4 = 0; k4 < 16; k4++) {
        float4 xv[8];
        #pragma unroll
        for (int rr = 0; rr < 8; rr++) {
            int r = rbase + 32 * rr;
            xv[rr] = (r < n) ? X4[(size_t)r * 16 + k4] : make_float4(0.f, 0.f, 0.f, 0.f);
        }
        if (BN) {
            float4 a4 = ((const float4*)sA)[k4];
            float4 c4 = ((const float4*)sC)[k4];
            #pragma unroll
            for (int rr = 0; rr < 8; rr++) {
                xv[rr].x = fmaxf(fmaf(a4.x, xv[rr].x, c4.x), 0.0f);
                xv[rr].y = fmaxf(fmaf(a4.y, xv[rr].y, c4.y), 0.0f);
                xv[rr].z = fmaxf(fmaf(a4.z, xv[rr].z, c4.z), 0.0f);
                xv[rr].w = fmaxf(fmaf(a4.w, xv[rr].w, c4.w), 0.0f);
            }
        }
        #pragma unroll
        for (int kk = 0; kk < 4; kk++) {
            const float* wrow = &sW[k4 * 4 + kk][cg * 8];
            float4 w0 = *(const float4*)(wrow);
            float4 w1 = *(const float4*)(wrow + 4);
            #pragma unroll
            for (int rr = 0; rr < 8; rr++) {
                float xk = ((const float*)&xv[rr])[kk];
                acc[rr][0] = fmaf(xk, w0.x, acc[rr][0]);
                acc[rr][1] = fmaf(xk, w0.y, acc[rr][1]);
                acc[rr][2] = fmaf(xk, w0.z, acc[rr][2]);
                acc[rr][3] = fmaf(xk, w0.w, acc[rr][3]);
                acc[rr][4] = fmaf(xk, w1.x, acc[rr][4]);
                acc[rr][5] = fmaf(xk, w1.y, acc[rr][5]);
                acc[rr][6] = fmaf(xk, w1.z, acc[rr][6]);
                acc[rr][7] = fmaf(xk, w1.w, acc[rr][7]);
            }
        }
    }

    #pragma unroll
    for (int rr = 0; rr < 8; rr++) {
        int r = rbase + 32 * rr;
        if (r < n) {
            float dv = g_dinv[r];
            __half2 p0 = __floats2half2_rn(acc[rr][0] * dv, acc[rr][1] * dv);
            __half2 p1 = __floats2half2_rn(acc[rr][2] * dv, acc[rr][3] * dv);
            __half2 p2 = __floats2half2_rn(acc[rr][4] * dv, acc[rr][5] * dv);
            __half2 p3 = __floats2half2_rn(acc[rr][6] * dv, acc[rr][7] * dv);
            uint4 st;
            st.x = *(unsigned*)&p0; st.y = *(unsigned*)&p1;
            st.z = *(unsigned*)&p2; st.w = *(unsigned*)&p3;
            ((uint4*)(Yh + (size_t)r * 64))[cg] = st;
        }
    }
}

// ---------------- aggregation: 8 lanes/node + block-staged edge packets ----
// out[i] = dinv[i] * ( H'[i] + sum_e w_e * H'[src_e] ) + bias   (fp32 accum)
// A block's 32 nodes own a CONTIGUOUS CSR range (rows padded to 8). The whole
// range is staged into smem with one coalesced pass; the hot loop reads
// packets via broadcast LDS.128 instead of 8x-redundant LDG.128 (cuts agg LDG
// count ~27%; LDS has a cheaper issue floor and skips the L1tex queue).
// Overflow beyond QUOTA falls back to direct gmem packet loads (correct, cold).
template <bool STATS, bool CLEAN>
__global__ void __launch_bounds__(256) k_agg(const __half* __restrict__ H,
                                             const float* __restrict__ bias,
                                             float* __restrict__ out, int n) {
    __shared__ __align__(16) unsigned long long sedge[QUOTA];
    int tid  = threadIdx.x;
    int sub  = tid >> 3;        // 0..31 node slot
    int l8   = tid & 7;         // feature group (8 halves = 16B)
    int blk0 = blockIdx.x * 32;
    int i    = blk0 + sub;

    // stage the block's contiguous edge range
    int rb = blk0 < n ? blk0 : n;
    int re = (blk0 + 32) < n ? (blk0 + 32) : n;
    int eBeg   = g_rowptr[rb];
    int nE     = g_rowptr[re] - eBeg;            // multiple of 8
    int nStage = nE < QUOTA ? nE : QUOTA;
    for (int k = tid; k < (nStage >> 1); k += 256)
        ((ulonglong2*)sedge)[k] = ((const ulonglong2*)(g_edge + eBeg))[k];
    __syncthreads();

    float acc[8];
    #pragma unroll
    for (int k = 0; k < 8; k++) acc[k] = 0.0f;

    if (i < n) {
        {   // self term (weight 1 in the dinv-scaled domain)
            uint4 u = ((const uint4*)(H + (size_t)i * 64))[l8];
            float2 f0 = __half22float2(*(const __half2*)&u.x);
            float2 f1 = __half22float2(*(const __half2*)&u.y);
            float2 f2 = __half22float2(*(const __half2*)&u.z);
            float2 f3 = __half22float2(*(const __half2*)&u.w);
            acc[0] = f0.x; acc[1] = f0.y; acc[2] = f1.x; acc[3] = f1.y;
            acc[4] = f2.x; acc[5] = f2.y; acc[6] = f3.x; acc[7] = f3.y;
        }

        int e   = g_rowptr[i];
        int end = g_rowptr[i + 1];   // e, end multiples of 8

        for (int base = e; base < end; base += 8) {
            unsigned long long p[8];
            int loc = base - eBeg;
            if (loc + 8 <= nStage) {             // smem packets (LDS.128 x4)
                ulonglong2 q0 = *(const ulonglong2*)(sedge + loc);
                ulonglong2 q1 = *(const ulonglong2*)(sedge + loc + 2);
                ulonglong2 q2 = *(const ulonglong2*)(sedge + loc + 4);
                ulonglong2 q3 = *(const ulonglong2*)(sedge + loc + 6);
                p[0]=q0.x; p[1]=q0.y; p[2]=q1.x; p[3]=q1.y;
                p[4]=q2.x; p[5]=q2.y; p[6]=q3.x; p[7]=q3.y;
            } else {                             // overflow fallback (gmem)
                const ulonglong2* pp = (const ulonglong2*)(g_edge + base);
                ulonglong2 q0 = pp[0], q1 = pp[1], q2 = pp[2], q3 = pp[3];
                p[0]=q0.x; p[1]=q0.y; p[2]=q1.x; p[3]=q1.y;
                p[4]=q2.x; p[5]=q2.y; p[6]=q3.x; p[7]=q3.y;
            }
            uint4 u[8];
            #pragma unroll
            for (int j = 0; j < 8; j++)
                u[j] = ((const uint4*)(H + (size_t)(unsigned)p[j] * 64))[l8];
            #pragma unroll
            for (int j = 0; j < 8; j++) {
                float wj = __uint_as_float((unsigned)(p[j] >> 32));
                #pragma unroll
                for (int q = 0; q < 4; q++) {
                    unsigned lo = (&u[j].x)[q];
                    float2 f = __half22float2(*(const __half2*)&lo);
                    acc[2*q]   = fmaf(wj, f.x, acc[2*q]);
                    acc[2*q+1] = fmaf(wj, f.y, acc[2*q+1]);
                }
            }
        }

        float dv = g_dinv[i];
        const float4* B4 = (const float4*)bias;
        float4 b0 = B4[l8 * 2], b1 = B4[l8 * 2 + 1];
        float4 o0 = make_float4(fmaf(dv, acc[0], b0.x), fmaf(dv, acc[1], b0.y),
                                fmaf(dv, acc[2], b0.z), fmaf(dv, acc[3], b0.w));
        float4 o1 = make_float4(fmaf(dv, acc[4], b1.x), fmaf(dv, acc[5], b1.y),
                                fmaf(dv, acc[6], b1.z), fmaf(dv, acc[7], b1.w));
        float4* O4 = (float4*)(out + (size_t)i * 64);
        O4[l8 * 2] = o0; O4[l8 * 2 + 1] = o1;
        acc[0]=o0.x; acc[1]=o0.y; acc[2]=o0.z; acc[3]=o0.w;
        acc[4]=o1.x; acc[5]=o1.y; acc[6]=o1.z; acc[7]=o1.w;
    } else {
        #pragma unroll
        for (int k = 0; k < 8; k++) acc[k] = 0.0f;
    }

    if (STATS) {
        __shared__ __align__(16) float sacc[32][68];
        float4* row = (float4*)&sacc[sub][l8 * 8];
        row[0] = make_float4(acc[0], acc[1], acc[2], acc[3]);
        row[1] = make_float4(acc[4], acc[5], acc[6], acc[7]);
        __syncthreads();
        if (tid < 64) {
            float s = 0.f, q = 0.f;
            #pragma unroll
            for (int k = 0; k < 32; k++) {
                float v = sacc[k][tid];
                s += v;
                q += v * v;
            }
            atomicAdd(&g_bnsum[tid], s);
            atomicAdd(&g_bnsq[tid],  q);
        }
    }

    if (CLEAN) {
        // restore all-zero invariant (everything else fully rewritten per call)
        int g = blockIdx.x * 256 + tid;
        if (g < n) g_degcnt[g] = 0ULL;
        if (g < DF) { g_bnsum[g] = 0.0f; g_bnsq[g] = 0.0f; }
        if (g == 0) g_scan_ctr = 0;
    }
}

// ---------------------------------------------------------------------------
// Fork resources: created once on the first (uncaptured correctness) call so
// nothing is created during graph capture; the event fork/join becomes
// parallel edges in the captured graph. GPU work is identical every call.
static cudaStream_t g_s2  = nullptr;
static cudaEvent_t  g_ev1 = nullptr;
static cudaEvent_t  g_ev2 = nullptr;

extern "C" void kernel_launch(void* const* d_in, const int* in_sizes, int n_in,
                              void* d_out, int out_size) {
    const float* x     = (const float*)d_in[0];
    const int*   ei    = (const int*)d_in[1];
    const float* ew    = (const float*)d_in[2];
    const float* W1    = (const float*)d_in[3];
    const float* b1    = (const float*)d_in[4];
    const float* gamma = (const float*)d_in[5];
    const float* beta  = (const float*)d_in[6];
    const float* W2    = (const float*)d_in[7];
    const float* b2    = (const float*)d_in[8];

    int N = in_sizes[0] / DF;
    int E = in_sizes[2];
    if (N > NN || E > EE) return;

    if (!g_s2) {
        cudaStreamCreateWithFlags(&g_s2, cudaStreamNonBlocking);
        cudaEventCreateWithFlags(&g_ev1, cudaEventDisableTiming);
        cudaEventCreateWithFlags(&g_ev2, cudaEventDisableTiming);
    }

    __half *p_h1, *p_h2;
    float *p_ha;
    cudaGetSymbolAddress((void**)&p_h1, g_h1);
    cudaGetSymbolAddress((void**)&p_ha, g_ha);
    cudaGetSymbolAddress((void**)&p_h2, g_h2);

    int nb = (N + 1023) / 1024;
    float invn = 1.0f / (float)N;

    // ---- CSR build chain (stream 0) ----
    if ((E & 3) == 0)
        k_edge_deg<<<(E / 4 + 255) / 256, 256>>>(ei, ew, E);
    else
        k_edge_deg_s<<<(E + 255) / 256, 256>>>(ei, ew, E);
    k_scan<<<nb, 1024>>>(N, nb);

    // ---- fork: GEMM1 (needs only dinv) runs concurrent with fill ----
    cudaEventRecord(g_ev1, 0);
    cudaStreamWaitEvent(g_s2, g_ev1, 0);
    k_gemm<false><<<(N + 127) / 128, 256, 0, g_s2>>>(x, W1, p_h1, N,
                                                     nullptr, nullptr, 0.f);
    cudaEventRecord(g_ev2, g_s2);

    if ((E & 1) == 0)
        k_fill<<<(E / 2 + 255) / 256, 256>>>(ei, ew, E);
    else
        k_fill_s<<<(E + 255) / 256, 256>>>(ei, ew, E);

    cudaStreamWaitEvent(0, g_ev2, 0);   // join before agg1

    // ---- serial tail (data-dependent) ----
    k_agg<true, false><<<(N + 31) / 32, 256>>>(p_h1, b1, p_ha, N);
    k_gemm<true><<<(N + 127) / 128, 256>>>(p_ha, W2, p_h2, N, gamma, beta, invn);
    k_agg<false, true><<<(N + 31) / 32, 256>>>(p_h2, b2, (float*)d_out, N);
}

// round 10
// speedup vs baseline: 1.5774x; 1.5774x over previous
#include <cuda_runtime.h>
#include <cuda_fp16.h>
#include <mma.h>
using namespace nvcuda;

#define DF   64
#define NN   100000
#define EE   1600000
#define EEP  (EE + 8 * NN)           // padded CSR capacity (rows padded to 8)
#define EPSV 1e-5f
#define WSCALE 268435456.0f          // 2^28 fixed-point weight scale
#define WINV   (1.0f / 268435456.0f)

// ---------------- scratch (device globals; zero-initialized at load) -------
// Invariant: every call leaves g_degcnt/g_bnsum/g_bnsq/g_scan_ctr all-zero
// (CLEAN tail in the final kernel), matching first-call zero-init. Everything
// else is fully rewritten every call (incl. g_edge pad slots, written by scan).
__device__ unsigned long long g_degcnt[NN]; // (cnt<<48) | fx28 weighted degree
__device__ float g_dinv[NN];
__device__ int   g_fill[NN];                // scan seeds with prefix; fill bumps
__device__ int   g_rowptr[NN + 1];          // padded exclusive prefix
__device__ unsigned long long g_edge[EEP];  // packed: (w_bits<<32) | src
__device__ __half g_h1[(size_t)NN * DF];    // dinv-scaled layer-1 features (fp16)
__device__ float  g_ha[(size_t)NN * DF];    // aggregated layer-1 output (fp32)
__device__ __half g_h2[(size_t)NN * DF];    // dinv-scaled layer-2 features (fp16)
__device__ float g_bnsum[DF];
__device__ float g_bnsq[DF];
__device__ int   g_part[128];
__device__ int   g_scan_ctr;

__device__ __forceinline__ unsigned long long pack_dc(float w) {
    return (1ULL << 48) | (unsigned long long)(fmaf(w, WSCALE, 0.5f));
}

// ---------------- edge pass 1: single packed atomic per edge ---------------
__global__ void k_edge_deg(const int* __restrict__ ei,
                           const float* __restrict__ w, int E) {
    int e4 = (blockIdx.x * blockDim.x + threadIdx.x) * 4;
    if (e4 + 3 < E) {
        int4   d4 = *(const int4*)&ei[E + e4];
        float4 w4 = *(const float4*)&w[e4];
        atomicAdd(&g_degcnt[d4.x], pack_dc(w4.x));
        atomicAdd(&g_degcnt[d4.y], pack_dc(w4.y));
        atomicAdd(&g_degcnt[d4.z], pack_dc(w4.z));
        atomicAdd(&g_degcnt[d4.w], pack_dc(w4.w));
    } else {
        for (int e = e4; e < E; e++)
            atomicAdd(&g_degcnt[ei[E + e]], pack_dc(w[e]));
    }
}
__global__ void k_edge_deg_s(const int* __restrict__ ei,
                             const float* __restrict__ w, int E) {
    int e = blockIdx.x * blockDim.x + threadIdx.x;
    if (e < E) atomicAdd(&g_degcnt[ei[E + e]], pack_dc(w[e]));
}

// ---------------- fused scan: dinv + padded prefix + pad-slot zeroing ------
__global__ void k_scan(int n, int nb) {
    __shared__ int s[1024];
    __shared__ int sp[128];
    int t = threadIdx.x;
    int i = blockIdx.x * 1024 + t;

    int cnt = 0, v = 0;
    if (i < n) {
        unsigned long long p = g_degcnt[i];
        cnt = (int)(p >> 48);
        float deg = (float)(long long)(p & 0xFFFFFFFFFFFFULL) * WINV;
        g_dinv[i] = rsqrtf(deg + 1.0f);        // +1 = self loop
        v = (cnt + 7) & ~7;                    // pad row to multiple of 8
    }

    s[t] = v;
    __syncthreads();
    for (int off = 512; off > 0; off >>= 1) {
        if (t < off) s[t] += s[t + off];
        __syncthreads();
    }
    if (t == 0) {
        g_part[blockIdx.x] = s[0];
        __threadfence();
        atomicAdd(&g_scan_ctr, 1);
    }
    __syncthreads();

    s[t] = v;
    __syncthreads();
    for (int off = 1; off < 1024; off <<= 1) {
        int a = (t >= off) ? s[t - off] : 0;
        __syncthreads();
        s[t] += a;
        __syncthreads();
    }

    if (t == 0) {
        while (atomicAdd(&g_scan_ctr, 0) < nb) { }
    }
    __syncthreads();

    if (t < 128) sp[t] = (t < nb) ? g_part[t] : 0;
    __syncthreads();
    #pragma unroll
    for (int off = 1; off < 128; off <<= 1) {
        int a = (t < 128 && t >= off) ? sp[t - off] : 0;
        __syncthreads();
        if (t < 128) sp[t] += a;
        __syncthreads();
    }

    int bp = (blockIdx.x > 0) ? sp[blockIdx.x - 1] : 0;
    if (i < n) {
        int p = bp + s[t] - v;                 // padded exclusive prefix
        g_rowptr[i] = p;
        g_fill[i]   = p;                       // seed fill cursor
        for (int k = p + cnt; k < p + v; k++)  // zero-weight pad slots
            g_edge[k] = 0ULL;
    }
    if (i == n - 1) g_rowptr[n] = bp + s[t];
}

// ---------------- edge pass 2: fill CSR (raw weight; no gathers) -----------
__device__ __forceinline__ unsigned long long pack_edge(float w, int s) {
    return ((unsigned long long)__float_as_uint(w) << 32) |
           (unsigned long long)(unsigned)s;
}
__global__ void k_fill(const int* __restrict__ ei,
                       const float* __restrict__ w, int E) {
    int e2 = (blockIdx.x * blockDim.x + threadIdx.x) * 2;
    if (e2 + 1 < E) {
        int2   sv = *(const int2*)&ei[e2];
        int2   dv = *(const int2*)&ei[E + e2];
        float2 wv = *(const float2*)&w[e2];
        int slot0 = atomicAdd(&g_fill[dv.x], 1);
        int slot1 = atomicAdd(&g_fill[dv.y], 1);
        g_edge[slot0] = pack_edge(wv.x, sv.x);
        g_edge[slot1] = pack_edge(wv.y, sv.y);
    } else if (e2 < E) {
        int slot = atomicAdd(&g_fill[ei[E + e2]], 1);
        g_edge[slot] = pack_edge(w[e2], ei[e2]);
    }
}
__global__ void k_fill_s(const int* __restrict__ ei,
                         const float* __restrict__ w, int E) {
    int e = blockIdx.x * blockDim.x + threadIdx.x;
    if (e < E) {
        int slot = atomicAdd(&g_fill[ei[E + e]], 1);
        g_edge[slot] = pack_edge(w[e], ei[e]);
    }
}

// ---------------- GEMM (tensor cores): Yh = dinv .* (f(X) @ W), fp16 out ---
// wmma m16n16k16, fp16 inputs, fp32 accumulate. 128-row tile, 8 warps, each
// warp owns 16 rows. BN=true applies y = relu(a*x+c) during fp16 staging.
// Shared: usm is a union region — first the fp16 A tile (18KB), then after
// all A-fragments are register-resident (syncthreads) the fp32 C staging
// (34KB) overlays it.
template <bool BN>
__global__ void __launch_bounds__(256) k_gemm(const float* __restrict__ X,
                                              const float* __restrict__ W,
                                              __half* __restrict__ Yh, int n,
                                              const float* __restrict__ gamma,
                                              const float* __restrict__ beta,
                                              float invn) {
    __shared__ __align__(16) char usm[128 * 68 * 4];     // 34 KB union A/C
    __shared__ __align__(16) __half sB[64][72];          // 9 KB W fp16
    __shared__ float sBNa[64], sBNc[64];
    __half (*sA)[72] = (__half(*)[72])usm;
    float  (*uC)[68] = (float(*)[68])usm;

    int tid  = threadIdx.x;
    int w    = tid >> 5;
    int lane = tid & 31;
    int rbase = blockIdx.x * 128;

    if (BN && tid < 64) {
        float mu   = g_bnsum[tid] * invn;
        float var  = g_bnsq[tid] * invn - mu * mu;
        float a    = gamma[tid] * rsqrtf(var + EPSV);
        sBNa[tid] = a;
        sBNc[tid] = beta[tid] - mu * a;
    }
    // stage W -> fp16 smem
    for (int idx = tid; idx < 64 * 16; idx += 256) {
        int r = idx >> 4, c4 = idx & 15;
        float4 v = ((const float4*)W)[idx];
        __half2 h0 = __floats2half2_rn(v.x, v.y);
        __half2 h1 = __floats2half2_rn(v.z, v.w);
        *(__half2*)&sB[r][c4 * 4]     = h0;
        *(__half2*)&sB[r][c4 * 4 + 2] = h1;
    }
    if (BN) __syncthreads();   // BN coeffs ready before A staging

    // stage A (128 x 64) -> fp16 smem, with optional BN+ReLU transform
    for (int idx = tid; idx < 128 * 16; idx += 256) {
        int r = idx >> 4, c4 = idx & 15;
        int gr = rbase + r;
        float4 v = (gr < n) ? ((const float4*)X)[(size_t)gr * 16 + c4]
                            : make_float4(0.f, 0.f, 0.f, 0.f);
        if (BN) {
            int c = c4 * 4;
            v.x = fmaxf(fmaf(sBNa[c],     v.x, sBNc[c]),     0.f);
            v.y = fmaxf(fmaf(sBNa[c + 1], v.y, sBNc[c + 1]), 0.f);
            v.z = fmaxf(fmaf(sBNa[c + 2], v.z, sBNc[c + 2]), 0.f);
            v.w = fmaxf(fmaf(sBNa[c + 3], v.w, sBNc[c + 3]), 0.f);
        }
        __half2 h0 = __floats2half2_rn(v.x, v.y);
        __half2 h1 = __floats2half2_rn(v.z, v.w);
        *(__half2*)&sA[r][c4 * 4]     = h0;
        *(__half2*)&sA[r][c4 * 4 + 2] = h1;
    }
    __syncthreads();

    // load this warp's 4 A fragments (16 rows x full K) into registers
    wmma::fragment<wmma::matrix_a, 16, 16, 16, __half, wmma::row_major> af[4];
    #pragma unroll
    for (int kt = 0; kt < 4; kt++)
        wmma::load_matrix_sync(af[kt], &sA[w * 16][kt * 16], 72);
    __syncthreads();   // all A frags resident; usm may now be reused as C

    // mma: 4 n-tiles x 4 k-steps, store fp32 C to smem
    #pragma unroll
    for (int nt = 0; nt < 4; nt++) {
        wmma::fragment<wmma::accumulator, 16, 16, 16, float> cf;
        wmma::fill_fragment(cf, 0.0f);
        #pragma unroll
        for (int kt = 0; kt < 4; kt++) {
            wmma::fragment<wmma::matrix_b, 16, 16, 16, __half, wmma::row_major> bf;
            wmma::load_matrix_sync(bf, &sB[kt * 16][nt * 16], 72);
            wmma::mma_sync(cf, af[kt], bf, cf);
        }
        wmma::store_matrix_sync(&uC[w * 16][nt * 16], cf, 68, wmma::mem_row_major);
    }
    __syncwarp();

    // epilogue: scale rows by dinv, convert fp16, store (warp owns 16 rows)
    int rl = lane & 15;
    int ch = lane >> 4;                 // column half: 0 or 1
    int r  = rbase + w * 16 + rl;
    if (r < n) {
        float dv = g_dinv[r];
        const float* crow = &uC[w * 16 + rl][ch * 32];
        uint4* dst = (uint4*)(Yh + (size_t)r * 64 + ch * 32);
        #pragma unroll
        for (int g = 0; g < 4; g++) {
            __half2 h0 = __floats2half2_rn(crow[8*g + 0] * dv, crow[8*g + 1] * dv);
            __half2 h1 = __floats2half2_rn(crow[8*g + 2] * dv, crow[8*g + 3] * dv);
            __half2 h2 = __floats2half2_rn(crow[8*g + 4] * dv, crow[8*g + 5] * dv);
            __half2 h3 = __floats2half2_rn(crow[8*g + 6] * dv, crow[8*g + 7] * dv);
            uint4 st;
            st.x = *(unsigned*)&h0; st.y = *(unsigned*)&h1;
            st.z = *(unsigned*)&h2; st.w = *(unsigned*)&h3;
            dst[g] = st;
        }
    }
}

// ---------------- aggregation: 8 lanes/node, 8 feats (16B fp16) per lane ---
// out[i] = dinv[i] * ( H'[i] + sum_e w_e * H'[src_e] ) + bias   (fp32 accum)
// Rows padded to multiples of 8 edges: no clamps, no branches; packet loads
// are aligned LDG.128 (broadcast across a node's 8 lanes -> coalesced).
template <bool STATS, bool CLEAN>
__global__ void __launch_bounds__(256) k_agg(const __half* __restrict__ H,
                                             const float* __restrict__ bias,
                                             float* __restrict__ out, int n) {
    int tid = threadIdx.x;
    int sub = tid >> 3;         // 0..31 node slot
    int l8  = tid & 7;          // feature group (8 halves = 16B)
    int i   = blockIdx.x * 32 + sub;

    float acc[8];
    #pragma unroll
    for (int k = 0; k < 8; k++) acc[k] = 0.0f;

    if (i < n) {
        {   // self term (weight 1 in the dinv-scaled domain)
            uint4 u = ((const uint4*)(H + (size_t)i * 64))[l8];
            float2 f0 = __half22float2(*(const __half2*)&u.x);
            float2 f1 = __half22float2(*(const __half2*)&u.y);
            float2 f2 = __half22float2(*(const __half2*)&u.z);
            float2 f3 = __half22float2(*(const __half2*)&u.w);
            acc[0] = f0.x; acc[1] = f0.y; acc[2] = f1.x; acc[3] = f1.y;
            acc[4] = f2.x; acc[5] = f2.y; acc[6] = f3.x; acc[7] = f3.y;
        }

        int e   = g_rowptr[i];
        int end = g_rowptr[i + 1];   // e, end multiples of 8

        for (int base = e; base < end; base += 8) {
            const ulonglong2* pp = (const ulonglong2*)(g_edge + base);
            ulonglong2 q0 = pp[0], q1 = pp[1], q2 = pp[2], q3 = pp[3];
            unsigned long long p[8] = { q0.x, q0.y, q1.x, q1.y,
                                        q2.x, q2.y, q3.x, q3.y };
            uint4 u[8];
            #pragma unroll
            for (int j = 0; j < 8; j++)
                u[j] = ((const uint4*)(H + (size_t)(unsigned)p[j] * 64))[l8];
            #pragma unroll
            for (int j = 0; j < 8; j++) {
                float wj = __uint_as_float((unsigned)(p[j] >> 32));
                #pragma unroll
                for (int q = 0; q < 4; q++) {
                    unsigned lo = (&u[j].x)[q];
                    float2 f = __half22float2(*(const __half2*)&lo);
                    acc[2*q]   = fmaf(wj, f.x, acc[2*q]);
                    acc[2*q+1] = fmaf(wj, f.y, acc[2*q+1]);
                }
            }
        }

        float dv = g_dinv[i];
        const float4* B4 = (const float4*)bias;
        float4 b0 = B4[l8 * 2], b1 = B4[l8 * 2 + 1];
        float4 o0 = make_float4(fmaf(dv, acc[0], b0.x), fmaf(dv, acc[1], b0.y),
                                fmaf(dv, acc[2], b0.z), fmaf(dv, acc[3], b0.w));
        float4 o1 = make_float4(fmaf(dv, acc[4], b1.x), fmaf(dv, acc[5], b1.y),
                                fmaf(dv, acc[6], b1.z), fmaf(dv, acc[7], b1.w));
        float4* O4 = (float4*)(out + (size_t)i * 64);
        O4[l8 * 2] = o0; O4[l8 * 2 + 1] = o1;
        acc[0]=o0.x; acc[1]=o0.y; acc[2]=o0.z; acc[3]=o0.w;
        acc[4]=o1.x; acc[5]=o1.y; acc[6]=o1.z; acc[7]=o1.w;
    } else {
        #pragma unroll
        for (int k = 0; k < 8; k++) acc[k] = 0.0f;
    }

    if (STATS) {
        __shared__ __align__(16) float sacc[32][68];
        float4* row = (float4*)&sacc[sub][l8 * 8];
        row[0] = make_float4(acc[0], acc[1], acc[2], acc[3]);
        row[1] = make_float4(acc[4], acc[5], acc[6], acc[7]);
        __syncthreads();
        if (tid < 64) {
            float s = 0.f, q = 0.f;
            #pragma unroll
            for (int k = 0; k < 32; k++) {
                float v = sacc[k][tid];
                s += v;
                q += v * v;
            }
            atomicAdd(&g_bnsum[tid], s);
            atomicAdd(&g_bnsq[tid],  q);
        }
    }

    if (CLEAN) {
        int g = blockIdx.x * 256 + tid;
        if (g < n) g_degcnt[g] = 0ULL;
        if (g < DF) { g_bnsum[g] = 0.0f; g_bnsq[g] = 0.0f; }
        if (g == 0) g_scan_ctr = 0;
    }
}

// ---------------------------------------------------------------------------
// Fork resources: created once on the first (uncaptured correctness) call.
static cudaStream_t g_s2  = nullptr;
static cudaEvent_t  g_ev1 = nullptr;
static cudaEvent_t  g_ev2 = nullptr;

extern "C" void kernel_launch(void* const* d_in, const int* in_sizes, int n_in,
                              void* d_out, int out_size) {
    const float* x     = (const float*)d_in[0];
    const int*   ei    = (const int*)d_in[1];
    const float* ew    = (const float*)d_in[2];
    const float* W1    = (const float*)d_in[3];
    const float* b1    = (const float*)d_in[4];
    const float* gamma = (const float*)d_in[5];
    const float* beta  = (const float*)d_in[6];
    const float* W2    = (const float*)d_in[7];
    const float* b2    = (const float*)d_in[8];

    int N = in_sizes[0] / DF;
    int E = in_sizes[2];
    if (N > NN || E > EE) return;

    if (!g_s2) {
        cudaStreamCreateWithFlags(&g_s2, cudaStreamNonBlocking);
        cudaEventCreateWithFlags(&g_ev1, cudaEventDisableTiming);
        cudaEventCreateWithFlags(&g_ev2, cudaEventDisableTiming);
    }

    __half *p_h1, *p_h2;
    float *p_ha;
    cudaGetSymbolAddress((void**)&p_h1, g_h1);
    cudaGetSymbolAddress((void**)&p_ha, g_ha);
    cudaGetSymbolAddress((void**)&p_h2, g_h2);

    int nb = (N + 1023) / 1024;
    float invn = 1.0f / (float)N;

    // ---- CSR build chain (stream 0) ----
    if ((E & 3) == 0)
        k_edge_deg<<<(E / 4 + 255) / 256, 256>>>(ei, ew, E);
    else
        k_edge_deg_s<<<(E + 255) / 256, 256>>>(ei, ew, E);
    k_scan<<<nb, 1024>>>(N, nb);

    // ---- fork: GEMM1 (needs only dinv) runs concurrent with fill ----
    cudaEventRecord(g_ev1, 0);
    cudaStreamWaitEvent(g_s2, g_ev1, 0);
    k_gemm<false><<<(N + 127) / 128, 256, 0, g_s2>>>(x, W1, p_h1, N,
                                                     nullptr, nullptr, 0.f);
    cudaEventRecord(g_ev2, g_s2);

    if ((E & 1) == 0)
        k_fill<<<(E / 2 + 255) / 256, 256>>>(ei, ew, E);
    else
        k_fill_s<<<(E + 255) / 256, 256>>>(ei, ew, E);

    cudaStreamWaitEvent(0, g_ev2, 0);   // join before agg1

    // ---- serial tail (data-dependent) ----
    k_agg<true, false><<<(N + 31) / 32, 256>>>(p_h1, b1, p_ha, N);
    k_gemm<true><<<(N + 127) / 128, 256>>>(p_ha, W2, p_h2, N, gamma, beta, invn);
    k_agg<false, true><<<(N + 31) / 32, 256>>>(p_h2, b2, (float*)d_out, N);
}

// round 11
// speedup vs baseline: 1.5802x; 1.0018x over previous
#include <cuda_runtime.h>
#include <cuda_fp16.h>
#include <mma.h>
using namespace nvcuda;

#define DF   64
#define NN   100000
#define EE   1600000
#define EEP  (EE + 8 * NN)           // padded CSR capacity (rows padded to 8)
#define EPSV 1e-5f
#define WSCALE 268435456.0f          // 2^28 fixed-point weight scale
#define WINV   (1.0f / 268435456.0f)

// ---------------- scratch (device globals; zero-initialized at load) -------
// Invariant: every call leaves g_degcnt/g_bnsum/g_bnsq/g_scan_ctr all-zero
// (CLEAN tail in the final kernel), matching first-call zero-init. Everything
// else is fully rewritten every call (incl. g_edge pad slots, written by scan).
__device__ unsigned long long g_degcnt[NN]; // (cnt<<48) | fx28 weighted degree
__device__ float g_dinv[NN];
__device__ int   g_fill[NN];                // scan seeds with prefix; fill bumps
__device__ int   g_rowptr[NN + 1];          // padded exclusive prefix
__device__ unsigned long long g_edge[EEP];  // packed: (w_bits<<32) | src
__device__ __half g_h1[(size_t)NN * DF];    // dinv-scaled layer-1 features (fp16)
__device__ __half g_hb[(size_t)NN * DF];    // aggregated layer-1 output (fp16)
__device__ __half g_h2[(size_t)NN * DF];    // dinv-scaled layer-2 features (fp16)
__device__ float g_bnsum[DF];
__device__ float g_bnsq[DF];
__device__ int   g_part[128];
__device__ int   g_scan_ctr;

__device__ __forceinline__ unsigned long long pack_dc(float w) {
    return (1ULL << 48) | (unsigned long long)(fmaf(w, WSCALE, 0.5f));
}

// ---------------- edge pass 1: single packed atomic per edge, 8/thread -----
__global__ void k_edge_deg(const int* __restrict__ ei,
                           const float* __restrict__ w, int E) {
    int e8 = (blockIdx.x * blockDim.x + threadIdx.x) * 8;
    if (e8 + 7 < E) {
        int4   d0 = *(const int4*)&ei[E + e8];
        int4   d1 = *(const int4*)&ei[E + e8 + 4];
        float4 w0 = *(const float4*)&w[e8];
        float4 w1 = *(const float4*)&w[e8 + 4];
        atomicAdd(&g_degcnt[d0.x], pack_dc(w0.x));
        atomicAdd(&g_degcnt[d0.y], pack_dc(w0.y));
        atomicAdd(&g_degcnt[d0.z], pack_dc(w0.z));
        atomicAdd(&g_degcnt[d0.w], pack_dc(w0.w));
        atomicAdd(&g_degcnt[d1.x], pack_dc(w1.x));
        atomicAdd(&g_degcnt[d1.y], pack_dc(w1.y));
        atomicAdd(&g_degcnt[d1.z], pack_dc(w1.z));
        atomicAdd(&g_degcnt[d1.w], pack_dc(w1.w));
    } else {
        for (int e = e8; e < E; e++)
            atomicAdd(&g_degcnt[ei[E + e]], pack_dc(w[e]));
    }
}

// ---------------- fused scan: dinv + padded prefix + pad-slot zeroing ------
__global__ void k_scan(int n, int nb) {
    __shared__ int s[1024];
    __shared__ int sp[128];
    int t = threadIdx.x;
    int i = blockIdx.x * 1024 + t;

    int cnt = 0, v = 0;
    if (i < n) {
        unsigned long long p = g_degcnt[i];
        cnt = (int)(p >> 48);
        float deg = (float)(long long)(p & 0xFFFFFFFFFFFFULL) * WINV;
        g_dinv[i] = rsqrtf(deg + 1.0f);        // +1 = self loop
        v = (cnt + 7) & ~7;                    // pad row to multiple of 8
    }

    s[t] = v;
    __syncthreads();
    for (int off = 512; off > 0; off >>= 1) {
        if (t < off) s[t] += s[t + off];
        __syncthreads();
    }
    if (t == 0) {
        g_part[blockIdx.x] = s[0];
        __threadfence();
        atomicAdd(&g_scan_ctr, 1);
    }
    __syncthreads();

    s[t] = v;
    __syncthreads();
    for (int off = 1; off < 1024; off <<= 1) {
        int a = (t >= off) ? s[t - off] : 0;
        __syncthreads();
        s[t] += a;
        __syncthreads();
    }

    if (t == 0) {
        while (atomicAdd(&g_scan_ctr, 0) < nb) { }
    }
    __syncthreads();

    if (t < 128) sp[t] = (t < nb) ? g_part[t] : 0;
    __syncthreads();
    #pragma unroll
    for (int off = 1; off < 128; off <<= 1) {
        int a = (t < 128 && t >= off) ? sp[t - off] : 0;
        __syncthreads();
        if (t < 128) sp[t] += a;
        __syncthreads();
    }

    int bp = (blockIdx.x > 0) ? sp[blockIdx.x - 1] : 0;
    if (i < n) {
        int p = bp + s[t] - v;                 // padded exclusive prefix
        g_rowptr[i] = p;
        g_fill[i]   = p;                       // seed fill cursor
        for (int k = p + cnt; k < p + v; k++)  // zero-weight pad slots
            g_edge[k] = 0ULL;
    }
    if (i == n - 1) g_rowptr[n] = bp + s[t];
}

// ---------------- edge pass 2: fill CSR (raw weight; no gathers), 4/thr ----
__device__ __forceinline__ unsigned long long pack_edge(float w, int s) {
    return ((unsigned long long)__float_as_uint(w) << 32) |
           (unsigned long long)(unsigned)s;
}
__global__ void k_fill(const int* __restrict__ ei,
                       const float* __restrict__ w, int E) {
    int e4 = (blockIdx.x * blockDim.x + threadIdx.x) * 4;
    if (e4 + 3 < E) {
        int4   sv = *(const int4*)&ei[e4];
        int4   dv = *(const int4*)&ei[E + e4];
        float4 wv = *(const float4*)&w[e4];
        int s0 = atomicAdd(&g_fill[dv.x], 1);
        int s1 = atomicAdd(&g_fill[dv.y], 1);
        int s2 = atomicAdd(&g_fill[dv.z], 1);
        int s3 = atomicAdd(&g_fill[dv.w], 1);
        g_edge[s0] = pack_edge(wv.x, sv.x);
        g_edge[s1] = pack_edge(wv.y, sv.y);
        g_edge[s2] = pack_edge(wv.z, sv.z);
        g_edge[s3] = pack_edge(wv.w, sv.w);
    } else {
        for (int e = e4; e < E; e++) {
            int slot = atomicAdd(&g_fill[ei[E + e]], 1);
            g_edge[slot] = pack_edge(w[e], ei[e]);
        }
    }
}

// ---------------- GEMM (tensor cores): Yh = dinv .* (f(X) @ W), fp16 out ---
// wmma m16n16k16, fp16 inputs, fp32 accumulate. 128-row tile, 8 warps, each
// warp owns 16 rows. BN=true applies y = relu(a*x+c) during fp16 staging.
// HALF_IN selects fp16 input matrix (layer 2) vs fp32 (layer 1).
template <bool BN, bool HALF_IN>
__global__ void __launch_bounds__(256) k_gemm(const void* __restrict__ Xv,
                                              const float* __restrict__ W,
                                              __half* __restrict__ Yh, int n,
                                              const float* __restrict__ gamma,
                                              const float* __restrict__ beta,
                                              float invn) {
    __shared__ __align__(16) char usm[128 * 68 * 4];     // 34 KB union A/C
    __shared__ __align__(16) __half sB[64][72];          // 9 KB W fp16
    __shared__ float sBNa[64], sBNc[64];
    __half (*sA)[72] = (__half(*)[72])usm;
    float  (*uC)[68] = (float(*)[68])usm;

    int tid  = threadIdx.x;
    int w    = tid >> 5;
    int lane = tid & 31;
    int rbase = blockIdx.x * 128;

    if (BN && tid < 64) {
        float mu   = g_bnsum[tid] * invn;
        float var  = g_bnsq[tid] * invn - mu * mu;
        float a    = gamma[tid] * rsqrtf(var + EPSV);
        sBNa[tid] = a;
        sBNc[tid] = beta[tid] - mu * a;
    }
    // stage W -> fp16 smem
    for (int idx = tid; idx < 64 * 16; idx += 256) {
        int r = idx >> 4, c4 = idx & 15;
        float4 v = ((const float4*)W)[idx];
        __half2 h0 = __floats2half2_rn(v.x, v.y);
        __half2 h1 = __floats2half2_rn(v.z, v.w);
        *(__half2*)&sB[r][c4 * 4]     = h0;
        *(__half2*)&sB[r][c4 * 4 + 2] = h1;
    }
    if (BN) __syncthreads();   // BN coeffs ready before A staging

    // stage A (128 x 64) -> fp16 smem, with optional BN+ReLU transform
    if (HALF_IN) {
        const __half* X = (const __half*)Xv;
        for (int idx = tid; idx < 128 * 8; idx += 256) {
            int r = idx >> 3, c8 = idx & 7;
            int gr = rbase + r;
            uint4 v = (gr < n) ? ((const uint4*)X)[(size_t)gr * 8 + c8]
                               : make_uint4(0, 0, 0, 0);
            if (BN) {
                #pragma unroll
                for (int q = 0; q < 4; q++) {
                    unsigned lo = (&v.x)[q];
                    float2 f = __half22float2(*(const __half2*)&lo);
                    int c = c8 * 8 + q * 2;
                    f.x = fmaxf(fmaf(sBNa[c],     f.x, sBNc[c]),     0.f);
                    f.y = fmaxf(fmaf(sBNa[c + 1], f.y, sBNc[c + 1]), 0.f);
                    __half2 h = __floats2half2_rn(f.x, f.y);
                    (&v.x)[q] = *(unsigned*)&h;
                }
            }
            *(uint4*)&sA[r][c8 * 8] = v;
        }
    } else {
        const float* X = (const float*)Xv;
        for (int idx = tid; idx < 128 * 16; idx += 256) {
            int r = idx >> 4, c4 = idx & 15;
            int gr = rbase + r;
            float4 v = (gr < n) ? ((const float4*)X)[(size_t)gr * 16 + c4]
                                : make_float4(0.f, 0.f, 0.f, 0.f);
            if (BN) {
                int c = c4 * 4;
                v.x = fmaxf(fmaf(sBNa[c],     v.x, sBNc[c]),     0.f);
                v.y = fmaxf(fmaf(sBNa[c + 1], v.y, sBNc[c + 1]), 0.f);
                v.z = fmaxf(fmaf(sBNa[c + 2], v.z, sBNc[c + 2]), 0.f);
                v.w = fmaxf(fmaf(sBNa[c + 3], v.w, sBNc[c + 3]), 0.f);
            }
            __half2 h0 = __floats2half2_rn(v.x, v.y);
            __half2 h1 = __floats2half2_rn(v.z, v.w);
            *(__half2*)&sA[r][c4 * 4]     = h0;
            *(__half2*)&sA[r][c4 * 4 + 2] = h1;
        }
    }
    __syncthreads();

    // load this warp's 4 A fragments (16 rows x full K) into registers
    wmma::fragment<wmma::matrix_a, 16, 16, 16, __half, wmma::row_major> af[4];
    #pragma unroll
    for (int kt = 0; kt < 4; kt++)
        wmma::load_matrix_sync(af[kt], &sA[w * 16][kt * 16], 72);
    __syncthreads();   // all A frags resident; usm may now be reused as C

    // mma: 4 n-tiles x 4 k-steps, store fp32 C to smem
    #pragma unroll
    for (int nt = 0; nt < 4; nt++) {
        wmma::fragment<wmma::accumulator, 16, 16, 16, float> cf;
        wmma::fill_fragment(cf, 0.0f);
        #pragma unroll
        for (int kt = 0; kt < 4; kt++) {
            wmma::fragment<wmma::matrix_b, 16, 16, 16, __half, wmma::row_major> bf;
            wmma::load_matrix_sync(bf, &sB[kt * 16][nt * 16], 72);
            wmma::mma_sync(cf, af[kt], bf, cf);
        }
        wmma::store_matrix_sync(&uC[w * 16][nt * 16], cf, 68, wmma::mem_row_major);
    }
    __syncwarp();

    // epilogue: scale rows by dinv, convert fp16, store (warp owns 16 rows)
    int rl = lane & 15;
    int ch = lane >> 4;                 // column half: 0 or 1
    int r  = rbase + w * 16 + rl;
    if (r < n) {
        float dv = g_dinv[r];
        const float* crow = &uC[w * 16 + rl][ch * 32];
        uint4* dst = (uint4*)(Yh + (size_t)r * 64 + ch * 32);
        #pragma unroll
        for (int g = 0; g < 4; g++) {
            __half2 h0 = __floats2half2_rn(crow[8*g + 0] * dv, crow[8*g + 1] * dv);
            __half2 h1 = __floats2half2_rn(crow[8*g + 2] * dv, crow[8*g + 3] * dv);
            __half2 h2 = __floats2half2_rn(crow[8*g + 4] * dv, crow[8*g + 5] * dv);
            __half2 h3 = __floats2half2_rn(crow[8*g + 6] * dv, crow[8*g + 7] * dv);
            uint4 st;
            st.x = *(unsigned*)&h0; st.y = *(unsigned*)&h1;
            st.z = *(unsigned*)&h2; st.w = *(unsigned*)&h3;
            dst[g] = st;
        }
    }
}

// ---------------- aggregation: 8 lanes/node, 8 feats (16B fp16) per lane ---
// out[i] = dinv[i] * ( H'[i] + sum_e w_e * H'[src_e] ) + bias   (fp32 accum)
// HALF_OUT: store fp16 (layer 1 -> gemm2 input); else fp32 (final output).
// Stats are computed from the pre-rounding fp32 values.
template <bool STATS, bool CLEAN, bool HALF_OUT>
__global__ void __launch_bounds__(256, 3) k_agg(const __half* __restrict__ H,
                                                const float* __restrict__ bias,
                                                void* __restrict__ outv, int n) {
    int tid = threadIdx.x;
    int sub = tid >> 3;         // 0..31 node slot
    int l8  = tid & 7;          // feature group (8 halves = 16B)
    int i   = blockIdx.x * 32 + sub;

    float acc[8];
    #pragma unroll
    for (int k = 0; k < 8; k++) acc[k] = 0.0f;

    if (i < n) {
        {   // self term (weight 1 in the dinv-scaled domain)
            uint4 u = ((const uint4*)(H + (size_t)i * 64))[l8];
            float2 f0 = __half22float2(*(const __half2*)&u.x);
            float2 f1 = __half22float2(*(const __half2*)&u.y);
            float2 f2 = __half22float2(*(const __half2*)&u.z);
            float2 f3 = __half22float2(*(const __half2*)&u.w);
            acc[0] = f0.x; acc[1] = f0.y; acc[2] = f1.x; acc[3] = f1.y;
            acc[4] = f2.x; acc[5] = f2.y; acc[6] = f3.x; acc[7] = f3.y;
        }

        int e   = g_rowptr[i];
        int end = g_rowptr[i + 1];   // e, end multiples of 8

        for (int base = e; base < end; base += 8) {
            const ulonglong2* pp = (const ulonglong2*)(g_edge + base);
            ulonglong2 q0 = pp[0], q1 = pp[1], q2 = pp[2], q3 = pp[3];
            unsigned long long p[8] = { q0.x, q0.y, q1.x, q1.y,
                                        q2.x, q2.y, q3.x, q3.y };
            uint4 u[8];
            #pragma unroll
            for (int j = 0; j < 8; j++)
                u[j] = ((const uint4*)(H + (size_t)(unsigned)p[j] * 64))[l8];
            #pragma unroll
            for (int j = 0; j < 8; j++) {
                float wj = __uint_as_float((unsigned)(p[j] >> 32));
                #pragma unroll
                for (int q = 0; q < 4; q++) {
                    unsigned lo = (&u[j].x)[q];
                    float2 f = __half22float2(*(const __half2*)&lo);
                    acc[2*q]   = fmaf(wj, f.x, acc[2*q]);
                    acc[2*q+1] = fmaf(wj, f.y, acc[2*q+1]);
                }
            }
        }

        float dv = g_dinv[i];
        const float4* B4 = (const float4*)bias;
        float4 b0 = B4[l8 * 2], b1 = B4[l8 * 2 + 1];
        #pragma unroll
        for (int k = 0; k < 4; k++) acc[k]     = fmaf(dv, acc[k],     (&b0.x)[k]);
        #pragma unroll
        for (int k = 0; k < 4; k++) acc[k + 4] = fmaf(dv, acc[k + 4], (&b1.x)[k]);

        if (HALF_OUT) {
            __half* out = (__half*)outv;
            __half2 h0 = __floats2half2_rn(acc[0], acc[1]);
            __half2 h1 = __floats2half2_rn(acc[2], acc[3]);
            __half2 h2 = __floats2half2_rn(acc[4], acc[5]);
            __half2 h3 = __floats2half2_rn(acc[6], acc[7]);
            uint4 st;
            st.x = *(unsigned*)&h0; st.y = *(unsigned*)&h1;
            st.z = *(unsigned*)&h2; st.w = *(unsigned*)&h3;
            ((uint4*)(out + (size_t)i * 64))[l8] = st;
        } else {
            float* out = (float*)outv;
            float4* O4 = (float4*)(out + (size_t)i * 64);
            O4[l8 * 2]     = make_float4(acc[0], acc[1], acc[2], acc[3]);
            O4[l8 * 2 + 1] = make_float4(acc[4], acc[5], acc[6], acc[7]);
        }
    } else {
        #pragma unroll
        for (int k = 0; k < 8; k++) acc[k] = 0.0f;
    }

    if (STATS) {
        __shared__ __align__(16) float sacc[32][68];
        float4* row = (float4*)&sacc[sub][l8 * 8];
        row[0] = make_float4(acc[0], acc[1], acc[2], acc[3]);
        row[1] = make_float4(acc[4], acc[5], acc[6], acc[7]);
        __syncthreads();
        if (tid < 64) {
            float s = 0.f, q = 0.f;
            #pragma unroll
            for (int k = 0; k < 32; k++) {
                float v = sacc[k][tid];
                s += v;
                q += v * v;
            }
            atomicAdd(&g_bnsum[tid], s);
            atomicAdd(&g_bnsq[tid],  q);
        }
    }

    if (CLEAN) {
        int g = blockIdx.x * 256 + tid;
        if (g < n) g_degcnt[g] = 0ULL;
        if (g < DF) { g_bnsum[g] = 0.0f; g_bnsq[g] = 0.0f; }
        if (g == 0) g_scan_ctr = 0;
    }
}

// ---------------------------------------------------------------------------
// Fork resources: created once on the first (uncaptured correctness) call.
static cudaStream_t g_s2  = nullptr;
static cudaEvent_t  g_ev1 = nullptr;
static cudaEvent_t  g_ev2 = nullptr;

extern "C" void kernel_launch(void* const* d_in, const int* in_sizes, int n_in,
                              void* d_out, int out_size) {
    const float* x     = (const float*)d_in[0];
    const int*   ei    = (const int*)d_in[1];
    const float* ew    = (const float*)d_in[2];
    const float* W1    = (const float*)d_in[3];
    const float* b1    = (const float*)d_in[4];
    const float* gamma = (const float*)d_in[5];
    const float* beta  = (const float*)d_in[6];
    const float* W2    = (const float*)d_in[7];
    const float* b2    = (const float*)d_in[8];

    int N = in_sizes[0] / DF;
    int E = in_sizes[2];
    if (N > NN || E > EE) return;

    if (!g_s2) {
        cudaStreamCreateWithFlags(&g_s2, cudaStreamNonBlocking);
        cudaEventCreateWithFlags(&g_ev1, cudaEventDisableTiming);
        cudaEventCreateWithFlags(&g_ev2, cudaEventDisableTiming);
    }

    __half *p_h1, *p_hb, *p_h2;
    cudaGetSymbolAddress((void**)&p_h1, g_h1);
    cudaGetSymbolAddress((void**)&p_hb, g_hb);
    cudaGetSymbolAddress((void**)&p_h2, g_h2);

    int nb = (N + 1023) / 1024;
    float invn = 1.0f / (float)N;

    // ---- CSR build chain (stream 0) ----
    k_edge_deg<<<(E / 8 + 255) / 256 + 1, 256>>>(ei, ew, E);
    k_scan<<<nb, 1024>>>(N, nb);

    // ---- fork: GEMM1 (needs only dinv) runs concurrent with fill ----
    cudaEventRecord(g_ev1, 0);
    cudaStreamWaitEvent(g_s2, g_ev1, 0);
    k_gemm<false, false><<<(N + 127) / 128, 256, 0, g_s2>>>(
        x, W1, p_h1, N, nullptr, nullptr, 0.f);
    cudaEventRecord(g_ev2, g_s2);

    k_fill<<<(E / 4 + 255) / 256 + 1, 256>>>(ei, ew, E);

    cudaStreamWaitEvent(0, g_ev2, 0);   // join before agg1

    // ---- serial tail (data-dependent) ----
    k_agg<true, false, true><<<(N + 31) / 32, 256>>>(p_h1, b1, p_hb, N);
    k_gemm<true, true><<<(N + 127) / 128, 256>>>(
        p_hb, W2, p_h2, N, gamma, beta, invn);
    k_agg<false, true, false><<<(N + 31) / 32, 256>>>(p_h2, b2, d_out, N);
}